// round 5
// baseline (speedup 1.0000x reference)
#include <cuda_runtime.h>
#include <cuda_bf16.h>
#include <math_constants.h>

// Problem constants (fixed by the reference): B=4, H=8, S=2048, D=3
#define BATCH 4
#define HEADS 8
#define SEQ   2048
#define NGROUP (SEQ / 4)   // 512 groups of 4 keys
#define NCHUNK 8           // q-chunks per (b,h); 256 q per CTA
#define QCHUNK 256
#define NTHREADS 256       // thread = (pair p in 0..127, key-half in 0..1)

typedef unsigned long long u64;

__device__ __forceinline__ float ex2f(float x) {
    float y; asm("ex2.approx.f32 %0, %1;" : "=f"(y) : "f"(x)); return y;
}
__device__ __forceinline__ float rcpf(float x) {
    float y; asm("rcp.approx.f32 %0, %1;" : "=f"(y) : "f"(x)); return y;
}
__device__ __forceinline__ u64 fma2(u64 a, u64 b, u64 c) {
    u64 d; asm("fma.rn.f32x2 %0, %1, %2, %3;" : "=l"(d) : "l"(a), "l"(b), "l"(c)); return d;
}
__device__ __forceinline__ u64 mul2(u64 a, u64 b) {
    u64 d; asm("mul.rn.f32x2 %0, %1, %2;" : "=l"(d) : "l"(a), "l"(b)); return d;
}
__device__ __forceinline__ u64 add2(u64 a, u64 b) {
    u64 d; asm("add.rn.f32x2 %0, %1, %2;" : "=l"(d) : "l"(a), "l"(b)); return d;
}
__device__ __forceinline__ u64 pack2(float lo, float hi) {
    u64 d; asm("mov.b64 %0, {%1, %2};" : "=l"(d) : "f"(lo), "f"(hi)); return d;
}
__device__ __forceinline__ void unpack2(u64 v, float& lo, float& hi) {
    asm("mov.b64 {%0, %1}, %2;" : "=f"(lo), "=f"(hi) : "l"(v));
}

__global__ __launch_bounds__(NTHREADS)
void attn_kernel(const float* __restrict__ x,
                 const float* __restrict__ Wq,
                 const float* __restrict__ Wk,
                 const float* __restrict__ Wv,
                 float* __restrict__ out)
{
    // SoA over 4-key groups; 6 * 8KB = 48KB static shared (at the limit).
    // sK0 is reused as the split-K staging buffer in the epilogue.
    __shared__ float4 sK0[NGROUP], sK1[NGROUP], sK2[NGROUP];
    __shared__ float4 sV0[NGROUP], sV1[NGROUP], sV2[NGROUP];

    const int bh  = blockIdx.x;        // b*8 + h
    const int b   = bh >> 3;
    const int h   = bh & 7;
    const int tid = threadIdx.x;

    const float* wkp = Wk + h * 9;
    const float* wvp = Wv + h * 9;
    float wk[9], wv[9];
#pragma unroll
    for (int i = 0; i < 9; i++) { wk[i] = __ldg(wkp + i); wv[i] = __ldg(wvp + i); }

    const float* xb = x + b * SEQ * 3;

    // Build K,V in 4-key SoA packs (2 groups per thread).
#pragma unroll
    for (int g = tid; g < NGROUP; g += NTHREADS) {
        const float4* xp = reinterpret_cast<const float4*>(xb + 12 * g);
        const float4 xa = xp[0], xc = xp[1], xd = xp[2];
        const float X0[4] = { xa.x, xa.w, xc.z, xd.y };
        const float X1[4] = { xa.y, xc.x, xc.w, xd.z };
        const float X2[4] = { xa.z, xc.y, xd.x, xd.w };
        float4 K0, K1, K2, V0, V1, V2;
        float* k0 = &K0.x; float* k1 = &K1.x; float* k2 = &K2.x;
        float* v0 = &V0.x; float* v1 = &V1.x; float* v2 = &V2.x;
#pragma unroll
        for (int j = 0; j < 4; j++) {
            k0[j] = fmaf(X2[j], wk[6], fmaf(X1[j], wk[3], X0[j] * wk[0]));
            k1[j] = fmaf(X2[j], wk[7], fmaf(X1[j], wk[4], X0[j] * wk[1]));
            k2[j] = fmaf(X2[j], wk[8], fmaf(X1[j], wk[5], X0[j] * wk[2]));
            v0[j] = fmaf(X2[j], wv[6], fmaf(X1[j], wv[3], X0[j] * wv[0]));
            v1[j] = fmaf(X2[j], wv[7], fmaf(X1[j], wv[4], X0[j] * wv[1]));
            v2[j] = fmaf(X2[j], wv[8], fmaf(X1[j], wv[5], X0[j] * wv[2]));
        }
        sK0[g] = K0; sK1[g] = K1; sK2[g] = K2;
        sV0[g] = V0; sV1[g] = V1; sV2[g] = V2;
    }
    __syncthreads();

    // Thread decomposition: pair index owns queries (qA, qB); half selects
    // which half of the key range this thread scans.
    const int pp   = tid & 127;        // pair index 0..127
    const int half = tid >> 7;         // 0 or 1
    const int qA = blockIdx.y * QCHUNK + 2 * pp;   // 0..QCHUNK-2 within chunk
    const int qB = qA + 1;

    // Queries, pre-scaled by log2(e)/sqrt(3) (no row-max pass: bounded scores,
    // softmax shift-invariant; validated rel_err 4.8e-7 in R3).
    const float cs = 1.4426950408889634f * 0.5773502691896258f;
    const float* wqp = Wq + h * 9;
    const float w0 = __ldg(wqp + 0), w1 = __ldg(wqp + 1), w2 = __ldg(wqp + 2);
    const float w3 = __ldg(wqp + 3), w4 = __ldg(wqp + 4), w5 = __ldg(wqp + 5);
    const float w6 = __ldg(wqp + 6), w7 = __ldg(wqp + 7), w8 = __ldg(wqp + 8);

    const float xa0 = xb[3 * qA + 0], xa1 = xb[3 * qA + 1], xa2 = xb[3 * qA + 2];
    const float xb0 = xb[3 * qB + 0], xb1 = xb[3 * qB + 1], xb2 = xb[3 * qB + 2];
    const float qa0 = fmaf(xa2, w6, fmaf(xa1, w3, xa0 * w0)) * cs;
    const float qa1 = fmaf(xa2, w7, fmaf(xa1, w4, xa0 * w1)) * cs;
    const float qa2 = fmaf(xa2, w8, fmaf(xa1, w5, xa0 * w2)) * cs;
    const float qb0 = fmaf(xb2, w6, fmaf(xb1, w3, xb0 * w0)) * cs;
    const float qb1 = fmaf(xb2, w7, fmaf(xb1, w4, xb0 * w1)) * cs;
    const float qb2 = fmaf(xb2, w8, fmaf(xb1, w5, xb0 * w2)) * cs;

    const u64 qa0p = pack2(qa0, qa0), qa1p = pack2(qa1, qa1), qa2p = pack2(qa2, qa2);
    const u64 qb0p = pack2(qb0, qb0), qb1p = pack2(qb1, qb1), qb2p = pack2(qb2, qb2);

    const ulonglong2* pK0 = reinterpret_cast<const ulonglong2*>(sK0);
    const ulonglong2* pK1 = reinterpret_cast<const ulonglong2*>(sK1);
    const ulonglong2* pK2 = reinterpret_cast<const ulonglong2*>(sK2);
    const ulonglong2* pV0 = reinterpret_cast<const ulonglong2*>(sV0);
    const ulonglong2* pV1 = reinterpret_cast<const ulonglong2*>(sV1);
    const ulonglong2* pV2 = reinterpret_cast<const ulonglong2*>(sV2);

    // Accumulators: query A and B, each {den, n0, n1, n2} as (lo,hi) f32x2 lanes.
    u64 Adl = 0, Adh = 0, Aa0l = 0, Aa0h = 0, Aa1l = 0, Aa1h = 0, Aa2l = 0, Aa2h = 0;
    u64 Bdl = 0, Bdh = 0, Ba0l = 0, Ba0h = 0, Ba1l = 0, Ba1h = 0, Ba2l = 0, Ba2h = 0;

    const int gbeg = half * (NGROUP / 2);
    const int gend = gbeg + (NGROUP / 2);

#pragma unroll 2
    for (int i = gbeg; i < gend; i++) {
        const ulonglong2 k0 = pK0[i];
        const ulonglong2 k1 = pK1[i];
        const ulonglong2 k2 = pK2[i];
        const ulonglong2 v0 = pV0[i];
        const ulonglong2 v1 = pV1[i];
        const ulonglong2 v2 = pV2[i];

        // Query A: scores for these 4 keys
        {
            const u64 tl = fma2(qa0p, k0.x, fma2(qa1p, k1.x, mul2(qa2p, k2.x)));
            const u64 th = fma2(qa0p, k0.y, fma2(qa1p, k1.y, mul2(qa2p, k2.y)));
            float t0, t1, t2, t3;
            unpack2(tl, t0, t1); unpack2(th, t2, t3);
            const u64 el = pack2(ex2f(t0), ex2f(t1));
            const u64 eh = pack2(ex2f(t2), ex2f(t3));
            Adl  = add2(Adl, el);           Adh  = add2(Adh, eh);
            Aa0l = fma2(el, v0.x, Aa0l);    Aa0h = fma2(eh, v0.y, Aa0h);
            Aa1l = fma2(el, v1.x, Aa1l);    Aa1h = fma2(eh, v1.y, Aa1h);
            Aa2l = fma2(el, v2.x, Aa2l);    Aa2h = fma2(eh, v2.y, Aa2h);
        }
        // Query B: scores for the same 4 keys
        {
            const u64 tl = fma2(qb0p, k0.x, fma2(qb1p, k1.x, mul2(qb2p, k2.x)));
            const u64 th = fma2(qb0p, k0.y, fma2(qb1p, k1.y, mul2(qb2p, k2.y)));
            float t0, t1, t2, t3;
            unpack2(tl, t0, t1); unpack2(th, t2, t3);
            const u64 el = pack2(ex2f(t0), ex2f(t1));
            const u64 eh = pack2(ex2f(t2), ex2f(t3));
            Bdl  = add2(Bdl, el);           Bdh  = add2(Bdh, eh);
            Ba0l = fma2(el, v0.x, Ba0l);    Ba0h = fma2(eh, v0.y, Ba0h);
            Ba1l = fma2(el, v1.x, Ba1l);    Ba1h = fma2(eh, v1.y, Ba1h);
            Ba2l = fma2(el, v2.x, Ba2l);    Ba2h = fma2(eh, v2.y, Ba2h);
        }
    }

    // Horizontal reduce each query's accumulators to 4 scalars.
    float u0, u1, u2, u3;
    unpack2(Adl, u0, u1); unpack2(Adh, u2, u3);  const float AdS  = (u0 + u1) + (u2 + u3);
    unpack2(Aa0l, u0, u1); unpack2(Aa0h, u2, u3); const float An0 = (u0 + u1) + (u2 + u3);
    unpack2(Aa1l, u0, u1); unpack2(Aa1h, u2, u3); const float An1 = (u0 + u1) + (u2 + u3);
    unpack2(Aa2l, u0, u1); unpack2(Aa2h, u2, u3); const float An2 = (u0 + u1) + (u2 + u3);
    unpack2(Bdl, u0, u1); unpack2(Bdh, u2, u3);  const float BdS  = (u0 + u1) + (u2 + u3);
    unpack2(Ba0l, u0, u1); unpack2(Ba0h, u2, u3); const float Bn0 = (u0 + u1) + (u2 + u3);
    unpack2(Ba1l, u0, u1); unpack2(Ba1h, u2, u3); const float Bn1 = (u0 + u1) + (u2 + u3);
    unpack2(Ba2l, u0, u1); unpack2(Ba2h, u2, u3); const float Bn2 = (u0 + u1) + (u2 + u3);

    // Split-K merge: half==1 stages its partials in (reused) sK0; half==0 combines.
    __syncthreads();   // all reads of K/V done
    float4* stage = reinterpret_cast<float4*>(sK0);
    if (half == 1) {
        stage[2 * pp + 0] = make_float4(AdS, An0, An1, An2);
        stage[2 * pp + 1] = make_float4(BdS, Bn0, Bn1, Bn2);
    }
    __syncthreads();
    if (half == 0) {
        const float4 sA = stage[2 * pp + 0];
        const float4 sB = stage[2 * pp + 1];
        const float invA = rcpf(AdS + sA.x);
        const float invB = rcpf(BdS + sB.x);
        const float oA0 = (An0 + sA.y) * invA;
        const float oA1 = (An1 + sA.z) * invA;
        const float oA2 = (An2 + sA.w) * invA;
        const float oB0 = (Bn0 + sB.y) * invB;
        const float oB1 = (Bn1 + sB.z) * invB;
        const float oB2 = (Bn2 + sB.w) * invB;

        const int base = (bh * SEQ + qA) * 3;   // qB = qA+1 -> 6 consecutive floats
        const int dup  = BATCH * HEADS * SEQ * 3;
        out[base + 0] = oA0; out[base + 1] = oA1; out[base + 2] = oA2;
        out[base + 3] = oB0; out[base + 4] = oB1; out[base + 5] = oB2;
        out[dup + base + 0] = oA0; out[dup + base + 1] = oA1; out[dup + base + 2] = oA2;
        out[dup + base + 3] = oB0; out[dup + base + 4] = oB1; out[dup + base + 5] = oB2;
    }
}

extern "C" void kernel_launch(void* const* d_in, const int* in_sizes, int n_in,
                              void* d_out, int out_size)
{
    const float* x  = (const float*)d_in[0];
    const float* Wq = (const float*)d_in[1];
    const float* Wk = (const float*)d_in[2];
    const float* Wv = (const float*)d_in[3];
    float* out = (float*)d_out;

    dim3 grid(BATCH * HEADS, NCHUNK);   // 32 x 8 = 256 CTAs (single wave @ 2 CTA/SM)
    attn_kernel<<<grid, NTHREADS>>>(x, Wq, Wk, Wv, out);
}

// round 6
// speedup vs baseline: 1.0083x; 1.0083x over previous
#include <cuda_runtime.h>
#include <cuda_bf16.h>
#include <math_constants.h>

// Problem constants (fixed by the reference): B=4, H=8, S=2048, D=3
#define BATCH 4
#define HEADS 8
#define SEQ   2048
#define NGROUP (SEQ / 4)   // 512 groups of 4 keys
#define NCHUNK 8           // q-chunks per (b,h); 256 q per CTA
#define QCHUNK 256
#define NTHREADS 384       // thread = (pair 0..127, key-third 0..2)
#define GSPLIT 171         // ceil(512/3); thirds: 171,171,170 groups

typedef unsigned long long u64;

__device__ __forceinline__ float ex2f(float x) {
    float y; asm("ex2.approx.f32 %0, %1;" : "=f"(y) : "f"(x)); return y;
}
__device__ __forceinline__ float rcpf(float x) {
    float y; asm("rcp.approx.f32 %0, %1;" : "=f"(y) : "f"(x)); return y;
}
__device__ __forceinline__ u64 fma2(u64 a, u64 b, u64 c) {
    u64 d; asm("fma.rn.f32x2 %0, %1, %2, %3;" : "=l"(d) : "l"(a), "l"(b), "l"(c)); return d;
}
__device__ __forceinline__ u64 mul2(u64 a, u64 b) {
    u64 d; asm("mul.rn.f32x2 %0, %1, %2;" : "=l"(d) : "l"(a), "l"(b)); return d;
}
__device__ __forceinline__ u64 add2(u64 a, u64 b) {
    u64 d; asm("add.rn.f32x2 %0, %1, %2;" : "=l"(d) : "l"(a), "l"(b)); return d;
}
__device__ __forceinline__ u64 pack2(float lo, float hi) {
    u64 d; asm("mov.b64 %0, {%1, %2};" : "=l"(d) : "f"(lo), "f"(hi)); return d;
}
__device__ __forceinline__ void unpack2(u64 v, float& lo, float& hi) {
    asm("mov.b64 {%0, %1}, %2;" : "=f"(lo), "=f"(hi) : "l"(v));
}

__global__ __launch_bounds__(NTHREADS, 2)
void attn_kernel(const float* __restrict__ x,
                 const float* __restrict__ Wq,
                 const float* __restrict__ Wk,
                 const float* __restrict__ Wv,
                 float* __restrict__ out)
{
    // SoA over 4-key groups; 6 * 8KB = 48KB static shared (at the limit).
    // sK0 (8KB) is reused as the split-K staging buffer in the epilogue.
    __shared__ float4 sK0[NGROUP], sK1[NGROUP], sK2[NGROUP];
    __shared__ float4 sV0[NGROUP], sV1[NGROUP], sV2[NGROUP];

    const int bh  = blockIdx.x;        // b*8 + h
    const int b   = bh >> 3;
    const int h   = bh & 7;
    const int tid = threadIdx.x;

    const float* wkp = Wk + h * 9;
    const float* wvp = Wv + h * 9;
    float wk[9], wv[9];
#pragma unroll
    for (int i = 0; i < 9; i++) { wk[i] = __ldg(wkp + i); wv[i] = __ldg(wvp + i); }

    const float* xb = x + b * SEQ * 3;

    // Build K,V in 4-key SoA packs.
    for (int g = tid; g < NGROUP; g += NTHREADS) {
        const float4* xp = reinterpret_cast<const float4*>(xb + 12 * g);
        const float4 xa = xp[0], xc = xp[1], xd = xp[2];
        const float X0[4] = { xa.x, xa.w, xc.z, xd.y };
        const float X1[4] = { xa.y, xc.x, xc.w, xd.z };
        const float X2[4] = { xa.z, xc.y, xd.x, xd.w };
        float4 K0, K1, K2, V0, V1, V2;
        float* k0 = &K0.x; float* k1 = &K1.x; float* k2 = &K2.x;
        float* v0 = &V0.x; float* v1 = &V1.x; float* v2 = &V2.x;
#pragma unroll
        for (int j = 0; j < 4; j++) {
            k0[j] = fmaf(X2[j], wk[6], fmaf(X1[j], wk[3], X0[j] * wk[0]));
            k1[j] = fmaf(X2[j], wk[7], fmaf(X1[j], wk[4], X0[j] * wk[1]));
            k2[j] = fmaf(X2[j], wk[8], fmaf(X1[j], wk[5], X0[j] * wk[2]));
            v0[j] = fmaf(X2[j], wv[6], fmaf(X1[j], wv[3], X0[j] * wv[0]));
            v1[j] = fmaf(X2[j], wv[7], fmaf(X1[j], wv[4], X0[j] * wv[1]));
            v2[j] = fmaf(X2[j], wv[8], fmaf(X1[j], wv[5], X0[j] * wv[2]));
        }
        sK0[g] = K0; sK1[g] = K1; sK2[g] = K2;
        sV0[g] = V0; sV1[g] = V1; sV2[g] = V2;
    }
    __syncthreads();

    // Thread decomposition: pair index owns queries (qA, qB); third selects
    // which third of the key range this thread scans.
    const int pp    = tid & 127;        // pair index 0..127
    const int third = tid >> 7;         // 0, 1, 2
    const int qA = blockIdx.y * QCHUNK + 2 * pp;
    const int qB = qA + 1;

    // Queries, pre-scaled by log2(e)/sqrt(3) (no row-max pass: bounded scores,
    // softmax shift-invariant; validated rel_err ~4e-7 in R3/R5).
    const float cs = 1.4426950408889634f * 0.5773502691896258f;
    const float* wqp = Wq + h * 9;
    const float w0 = __ldg(wqp + 0), w1 = __ldg(wqp + 1), w2 = __ldg(wqp + 2);
    const float w3 = __ldg(wqp + 3), w4 = __ldg(wqp + 4), w5 = __ldg(wqp + 5);
    const float w6 = __ldg(wqp + 6), w7 = __ldg(wqp + 7), w8 = __ldg(wqp + 8);

    const float xa0 = xb[3 * qA + 0], xa1 = xb[3 * qA + 1], xa2 = xb[3 * qA + 2];
    const float xb0 = xb[3 * qB + 0], xb1 = xb[3 * qB + 1], xb2 = xb[3 * qB + 2];
    const float qa0 = fmaf(xa2, w6, fmaf(xa1, w3, xa0 * w0)) * cs;
    const float qa1 = fmaf(xa2, w7, fmaf(xa1, w4, xa0 * w1)) * cs;
    const float qa2 = fmaf(xa2, w8, fmaf(xa1, w5, xa0 * w2)) * cs;
    const float qb0 = fmaf(xb2, w6, fmaf(xb1, w3, xb0 * w0)) * cs;
    const float qb1 = fmaf(xb2, w7, fmaf(xb1, w4, xb0 * w1)) * cs;
    const float qb2 = fmaf(xb2, w8, fmaf(xb1, w5, xb0 * w2)) * cs;

    const u64 qa0p = pack2(qa0, qa0), qa1p = pack2(qa1, qa1), qa2p = pack2(qa2, qa2);
    const u64 qb0p = pack2(qb0, qb0), qb1p = pack2(qb1, qb1), qb2p = pack2(qb2, qb2);

    const ulonglong2* pK0 = reinterpret_cast<const ulonglong2*>(sK0);
    const ulonglong2* pK1 = reinterpret_cast<const ulonglong2*>(sK1);
    const ulonglong2* pK2 = reinterpret_cast<const ulonglong2*>(sK2);
    const ulonglong2* pV0 = reinterpret_cast<const ulonglong2*>(sV0);
    const ulonglong2* pV1 = reinterpret_cast<const ulonglong2*>(sV1);
    const ulonglong2* pV2 = reinterpret_cast<const ulonglong2*>(sV2);

    // Accumulators: query A and B, each {den, n0, n1, n2} as (lo,hi) f32x2 lanes.
    u64 Adl = 0, Adh = 0, Aa0l = 0, Aa0h = 0, Aa1l = 0, Aa1h = 0, Aa2l = 0, Aa2h = 0;
    u64 Bdl = 0, Bdh = 0, Ba0l = 0, Ba0h = 0, Ba1l = 0, Ba1h = 0, Ba2l = 0, Ba2h = 0;

    const int gbeg = third * GSPLIT;                       // 0, 171, 342
    const int gend = (third == 2) ? NGROUP : gbeg + GSPLIT; // 171, 342, 512

#pragma unroll 2
    for (int i = gbeg; i < gend; i++) {
        const ulonglong2 k0 = pK0[i];
        const ulonglong2 k1 = pK1[i];
        const ulonglong2 k2 = pK2[i];
        const ulonglong2 v0 = pV0[i];
        const ulonglong2 v1 = pV1[i];
        const ulonglong2 v2 = pV2[i];

        // Query A: scores for these 4 keys
        {
            const u64 tl = fma2(qa0p, k0.x, fma2(qa1p, k1.x, mul2(qa2p, k2.x)));
            const u64 th = fma2(qa0p, k0.y, fma2(qa1p, k1.y, mul2(qa2p, k2.y)));
            float t0, t1, t2, t3;
            unpack2(tl, t0, t1); unpack2(th, t2, t3);
            const u64 el = pack2(ex2f(t0), ex2f(t1));
            const u64 eh = pack2(ex2f(t2), ex2f(t3));
            Adl  = add2(Adl, el);           Adh  = add2(Adh, eh);
            Aa0l = fma2(el, v0.x, Aa0l);    Aa0h = fma2(eh, v0.y, Aa0h);
            Aa1l = fma2(el, v1.x, Aa1l);    Aa1h = fma2(eh, v1.y, Aa1h);
            Aa2l = fma2(el, v2.x, Aa2l);    Aa2h = fma2(eh, v2.y, Aa2h);
        }
        // Query B: scores for the same 4 keys
        {
            const u64 tl = fma2(qb0p, k0.x, fma2(qb1p, k1.x, mul2(qb2p, k2.x)));
            const u64 th = fma2(qb0p, k0.y, fma2(qb1p, k1.y, mul2(qb2p, k2.y)));
            float t0, t1, t2, t3;
            unpack2(tl, t0, t1); unpack2(th, t2, t3);
            const u64 el = pack2(ex2f(t0), ex2f(t1));
            const u64 eh = pack2(ex2f(t2), ex2f(t3));
            Bdl  = add2(Bdl, el);           Bdh  = add2(Bdh, eh);
            Ba0l = fma2(el, v0.x, Ba0l);    Ba0h = fma2(eh, v0.y, Ba0h);
            Ba1l = fma2(el, v1.x, Ba1l);    Ba1h = fma2(eh, v1.y, Ba1h);
            Ba2l = fma2(el, v2.x, Ba2l);    Ba2h = fma2(eh, v2.y, Ba2h);
        }
    }

    // Horizontal reduce each query's accumulators to 4 scalars.
    float u0, u1, u2, u3;
    unpack2(Adl, u0, u1); unpack2(Adh, u2, u3);  const float AdS  = (u0 + u1) + (u2 + u3);
    unpack2(Aa0l, u0, u1); unpack2(Aa0h, u2, u3); const float An0 = (u0 + u1) + (u2 + u3);
    unpack2(Aa1l, u0, u1); unpack2(Aa1h, u2, u3); const float An1 = (u0 + u1) + (u2 + u3);
    unpack2(Aa2l, u0, u1); unpack2(Aa2h, u2, u3); const float An2 = (u0 + u1) + (u2 + u3);
    unpack2(Bdl, u0, u1); unpack2(Bdh, u2, u3);  const float BdS  = (u0 + u1) + (u2 + u3);
    unpack2(Ba0l, u0, u1); unpack2(Ba0h, u2, u3); const float Bn0 = (u0 + u1) + (u2 + u3);
    unpack2(Ba1l, u0, u1); unpack2(Ba1h, u2, u3); const float Bn1 = (u0 + u1) + (u2 + u3);
    unpack2(Ba2l, u0, u1); unpack2(Ba2h, u2, u3); const float Bn2 = (u0 + u1) + (u2 + u3);

    // Split-K merge: thirds 1 and 2 stage partials in (reused) sK0; third 0 combines.
    __syncthreads();   // all reads of K/V done
    float4* stage = reinterpret_cast<float4*>(sK0);   // 512 float4 = 8KB: [2 thirds][128 pairs][2 q]
    if (third != 0) {
        float4* sp = stage + (third - 1) * 256 + 2 * pp;
        sp[0] = make_float4(AdS, An0, An1, An2);
        sp[1] = make_float4(BdS, Bn0, Bn1, Bn2);
    }
    __syncthreads();
    if (third == 0) {
        const float4 s1A = stage[2 * pp + 0];
        const float4 s1B = stage[2 * pp + 1];
        const float4 s2A = stage[256 + 2 * pp + 0];
        const float4 s2B = stage[256 + 2 * pp + 1];
        const float invA = rcpf(AdS + s1A.x + s2A.x);
        const float invB = rcpf(BdS + s1B.x + s2B.x);
        const float oA0 = (An0 + s1A.y + s2A.y) * invA;
        const float oA1 = (An1 + s1A.z + s2A.z) * invA;
        const float oA2 = (An2 + s1A.w + s2A.w) * invA;
        const float oB0 = (Bn0 + s1B.y + s2B.y) * invB;
        const float oB1 = (Bn1 + s1B.z + s2B.z) * invB;
        const float oB2 = (Bn2 + s1B.w + s2B.w) * invB;

        const int base = (bh * SEQ + qA) * 3;   // qB = qA+1 -> 6 consecutive floats
        const int dup  = BATCH * HEADS * SEQ * 3;
        out[base + 0] = oA0; out[base + 1] = oA1; out[base + 2] = oA2;
        out[base + 3] = oB0; out[base + 4] = oB1; out[base + 5] = oB2;
        out[dup + base + 0] = oA0; out[dup + base + 1] = oA1; out[dup + base + 2] = oA2;
        out[dup + base + 3] = oB0; out[dup + base + 4] = oB1; out[dup + base + 5] = oB2;
    }
}

extern "C" void kernel_launch(void* const* d_in, const int* in_sizes, int n_in,
                              void* d_out, int out_size)
{
    const float* x  = (const float*)d_in[0];
    const float* Wq = (const float*)d_in[1];
    const float* Wk = (const float*)d_in[2];
    const float* Wv = (const float*)d_in[3];
    float* out = (float*)d_out;

    dim3 grid(BATCH * HEADS, NCHUNK);   // 32 x 8 = 256 CTAs, 2/SM -> single wave
    attn_kernel<<<grid, NTHREADS>>>(x, Wq, Wk, Wv, out);
}

// round 7
// speedup vs baseline: 1.0532x; 1.0445x over previous
#include <cuda_runtime.h>
#include <cuda_bf16.h>
#include <math_constants.h>

// Problem constants (fixed by the reference): B=4, H=8, S=2048, D=3
#define BATCH 4
#define HEADS 8
#define SEQ   2048
#define NGROUP (SEQ / 4)   // 512 groups of 4 keys
#define NCHUNK 8           // q-chunks per (b,h); 256 q per CTA
#define QCHUNK 256
#define NTHREADS 256       // thread = (quad 0..63, split 0..3)
#define GPT (NGROUP / 4)   // 128 groups per thread (split-K 4)

__device__ __forceinline__ float ex2f(float x) {
    float y; asm("ex2.approx.f32 %0, %1;" : "=f"(y) : "f"(x)); return y;
}
__device__ __forceinline__ float rcpf(float x) {
    float y; asm("rcp.approx.f32 %0, %1;" : "=f"(y) : "f"(x)); return y;
}

__global__ __launch_bounds__(NTHREADS, 2)
void attn_kernel(const float* __restrict__ x,
                 const float* __restrict__ Wq,
                 const float* __restrict__ Wk,
                 const float* __restrict__ Wv,
                 float* __restrict__ out)
{
    // One interleaved stream: group g = {K0,K1,K2,V0,V1,V2} float4s, 96B/group.
    // 512 * 96B = 48KB (at the static limit). Reused as split-K staging at the end.
    __shared__ float4 sKV[NGROUP * 6];

    const int bh  = blockIdx.x;        // b*8 + h
    const int b   = bh >> 3;
    const int h   = bh & 7;
    const int tid = threadIdx.x;

    const float* wkp = Wk + h * 9;
    const float* wvp = Wv + h * 9;
    float wk[9], wv[9];
#pragma unroll
    for (int i = 0; i < 9; i++) { wk[i] = __ldg(wkp + i); wv[i] = __ldg(wvp + i); }

    const float* xb = x + b * SEQ * 3;

    // Build K,V: 4-key packs, 6 contiguous float4s per group.
    for (int g = tid; g < NGROUP; g += NTHREADS) {
        const float4* xp = reinterpret_cast<const float4*>(xb + 12 * g);
        const float4 xa = xp[0], xc = xp[1], xd = xp[2];
        const float X0[4] = { xa.x, xa.w, xc.z, xd.y };
        const float X1[4] = { xa.y, xc.x, xc.w, xd.z };
        const float X2[4] = { xa.z, xc.y, xd.x, xd.w };
        float4 K0, K1, K2, V0, V1, V2;
        float* k0 = &K0.x; float* k1 = &K1.x; float* k2 = &K2.x;
        float* v0 = &V0.x; float* v1 = &V1.x; float* v2 = &V2.x;
#pragma unroll
        for (int j = 0; j < 4; j++) {
            k0[j] = fmaf(X2[j], wk[6], fmaf(X1[j], wk[3], X0[j] * wk[0]));
            k1[j] = fmaf(X2[j], wk[7], fmaf(X1[j], wk[4], X0[j] * wk[1]));
            k2[j] = fmaf(X2[j], wk[8], fmaf(X1[j], wk[5], X0[j] * wk[2]));
            v0[j] = fmaf(X2[j], wv[6], fmaf(X1[j], wv[3], X0[j] * wv[0]));
            v1[j] = fmaf(X2[j], wv[7], fmaf(X1[j], wv[4], X0[j] * wv[1]));
            v2[j] = fmaf(X2[j], wv[8], fmaf(X1[j], wv[5], X0[j] * wv[2]));
        }
        float4* dst = &sKV[6 * g];
        dst[0] = K0; dst[1] = K1; dst[2] = K2;
        dst[3] = V0; dst[4] = V1; dst[5] = V2;
    }
    __syncthreads();

    // Decomposition: quad owns 4 consecutive queries; split selects key quarter.
    const int quad  = tid & 63;
    const int split = tid >> 6;        // 0..3 (warp-uniform -> LDS broadcast)
    const int qbase = blockIdx.y * QCHUNK + 4 * quad;

    // Load x for the 4 queries (12 floats, 16B-aligned).
    const float4* xq = reinterpret_cast<const float4*>(xb + 3 * qbase);
    const float4 f0 = xq[0], f1 = xq[1], f2 = xq[2];

    // Project queries, pre-scaled by log2(e)/sqrt(3). (No row-max pass: scores
    // bounded far below f32 exp2 range; softmax shift-invariant. rel_err ~3e-7.)
    const float cs = 1.4426950408889634f * 0.5773502691896258f;
    const float* wqp = Wq + h * 9;
    const float w0 = __ldg(wqp + 0), w1 = __ldg(wqp + 1), w2 = __ldg(wqp + 2);
    const float w3 = __ldg(wqp + 3), w4 = __ldg(wqp + 4), w5 = __ldg(wqp + 5);
    const float w6 = __ldg(wqp + 6), w7 = __ldg(wqp + 7), w8 = __ldg(wqp + 8);

#define PROJQ(x0, x1, x2, qa, qb, qc) \
    const float qa = fmaf(x2, w6, fmaf(x1, w3, x0 * w0)) * cs; \
    const float qb = fmaf(x2, w7, fmaf(x1, w4, x0 * w1)) * cs; \
    const float qc = fmaf(x2, w8, fmaf(x1, w5, x0 * w2)) * cs;

    PROJQ(f0.x, f0.y, f0.z, qA0, qA1, qA2)
    PROJQ(f0.w, f1.x, f1.y, qB0, qB1, qB2)
    PROJQ(f1.z, f1.w, f2.x, qC0, qC1, qC2)
    PROJQ(f2.y, f2.z, f2.w, qD0, qD1, qD2)
#undef PROJQ

    // Per-query accumulators: den, n0, n1, n2 (scalar f32).
    float dA = 0.f, nA0 = 0.f, nA1 = 0.f, nA2 = 0.f;
    float dB = 0.f, nB0 = 0.f, nB1 = 0.f, nB2 = 0.f;
    float dC = 0.f, nC0 = 0.f, nC1 = 0.f, nC2 = 0.f;
    float dD = 0.f, nD0 = 0.f, nD1 = 0.f, nD2 = 0.f;

    const float4* p = &sKV[6 * (split * GPT)];

#pragma unroll 4
    for (int it = 0; it < GPT; ++it) {
        const float4 k0 = p[0];
        const float4 k1 = p[1];
        const float4 k2 = p[2];
        const float4 v0 = p[3];
        const float4 v1 = p[4];
        const float4 v2 = p[5];
        p += 6;

        // One query against one key lane: 3 FFMA + EX2 + FADD + 3 FFMA.
#define KEY(q0_, q1_, q2_, dd, a0, a1, a2, K0c, K1c, K2c, V0c, V1c, V2c)       \
        {                                                                      \
            const float t = fmaf(q0_, K0c, fmaf(q1_, K1c, q2_ * K2c));         \
            const float e = ex2f(t);                                           \
            dd += e;                                                           \
            a0 = fmaf(e, V0c, a0);                                             \
            a1 = fmaf(e, V1c, a1);                                             \
            a2 = fmaf(e, V2c, a2);                                             \
        }
#define QUERY(q0_, q1_, q2_, dd, a0, a1, a2)                                   \
        KEY(q0_, q1_, q2_, dd, a0, a1, a2, k0.x, k1.x, k2.x, v0.x, v1.x, v2.x) \
        KEY(q0_, q1_, q2_, dd, a0, a1, a2, k0.y, k1.y, k2.y, v0.y, v1.y, v2.y) \
        KEY(q0_, q1_, q2_, dd, a0, a1, a2, k0.z, k1.z, k2.z, v0.z, v1.z, v2.z) \
        KEY(q0_, q1_, q2_, dd, a0, a1, a2, k0.w, k1.w, k2.w, v0.w, v1.w, v2.w)

        QUERY(qA0, qA1, qA2, dA, nA0, nA1, nA2)
        QUERY(qB0, qB1, qB2, dB, nB0, nB1, nB2)
        QUERY(qC0, qC1, qC2, dC, nC0, nC1, nC2)
        QUERY(qD0, qD1, qD2, dD, nD0, nD1, nD2)
#undef QUERY
#undef KEY
    }

    // Split-K merge through reused smem. Splits 1..3 stage; split 0 combines.
    __syncthreads();   // all K/V reads done
    float4* stage = reinterpret_cast<float4*>(sKV);  // [3 splits][64 quads][4 q] = 12KB
    if (split != 0) {
        float4* sp = stage + ((split - 1) * 64 + quad) * 4;
        sp[0] = make_float4(dA, nA0, nA1, nA2);
        sp[1] = make_float4(dB, nB0, nB1, nB2);
        sp[2] = make_float4(dC, nC0, nC1, nC2);
        sp[3] = make_float4(dD, nD0, nD1, nD2);
    }
    __syncthreads();
    if (split == 0) {
        float4 acc[4] = {
            make_float4(dA, nA0, nA1, nA2),
            make_float4(dB, nB0, nB1, nB2),
            make_float4(dC, nC0, nC1, nC2),
            make_float4(dD, nD0, nD1, nD2)
        };
#pragma unroll
        for (int s = 0; s < 3; s++) {
            const float4* sp = stage + (s * 64 + quad) * 4;
#pragma unroll
            for (int qi = 0; qi < 4; qi++) {
                const float4 v = sp[qi];
                acc[qi].x += v.x; acc[qi].y += v.y;
                acc[qi].z += v.z; acc[qi].w += v.w;
            }
        }
        float o[12];
#pragma unroll
        for (int qi = 0; qi < 4; qi++) {
            const float inv = rcpf(acc[qi].x);
            o[3 * qi + 0] = acc[qi].y * inv;
            o[3 * qi + 1] = acc[qi].z * inv;
            o[3 * qi + 2] = acc[qi].w * inv;
        }
        const int base = (bh * SEQ + qbase) * 3;   // multiple of 12 -> 16B aligned
        const int dup  = BATCH * HEADS * SEQ * 3;
        float4* o1 = reinterpret_cast<float4*>(out + base);
        float4* o2 = reinterpret_cast<float4*>(out + dup + base);
        const float4 pk0 = make_float4(o[0], o[1], o[2],  o[3]);
        const float4 pk1 = make_float4(o[4], o[5], o[6],  o[7]);
        const float4 pk2 = make_float4(o[8], o[9], o[10], o[11]);
        o1[0] = pk0; o1[1] = pk1; o1[2] = pk2;
        o2[0] = pk0; o2[1] = pk1; o2[2] = pk2;
    }
}

extern "C" void kernel_launch(void* const* d_in, const int* in_sizes, int n_in,
                              void* d_out, int out_size)
{
    const float* x  = (const float*)d_in[0];
    const float* Wq = (const float*)d_in[1];
    const float* Wk = (const float*)d_in[2];
    const float* Wv = (const float*)d_in[3];
    float* out = (float*)d_out;

    dim3 grid(BATCH * HEADS, NCHUNK);   // 32 x 8 = 256 CTAs, 2/SM -> single wave
    attn_kernel<<<grid, NTHREADS>>>(x, Wq, Wk, Wv, out);
}

// round 9
// speedup vs baseline: 1.0951x; 1.0398x over previous
#include <cuda_runtime.h>
#include <cuda_bf16.h>
#include <math_constants.h>

// Problem constants (fixed by the reference): B=4, H=8, S=2048, D=3
#define BATCH 4
#define HEADS 8
#define SEQ   2048
#define NGROUP (SEQ / 4)   // 512 groups of 4 keys
#define NCHUNK 16          // q-chunks per (b,h)
#define QCHUNK 128         // queries per CTA
#define NTHREADS 256       // thread = (duo 0..63 [2 queries], split 0..3)
#define GPT (NGROUP / 4)   // 128 groups per split

typedef unsigned long long u64;

__device__ __forceinline__ float ex2f(float x) {
    float y; asm("ex2.approx.f32 %0, %1;" : "=f"(y) : "f"(x)); return y;
}
__device__ __forceinline__ float rcpf(float x) {
    float y; asm("rcp.approx.f32 %0, %1;" : "=f"(y) : "f"(x)); return y;
}
__device__ __forceinline__ u64 fma2(u64 a, u64 b, u64 c) {
    u64 d; asm("fma.rn.f32x2 %0, %1, %2, %3;" : "=l"(d) : "l"(a), "l"(b), "l"(c)); return d;
}
__device__ __forceinline__ u64 mul2(u64 a, u64 b) {
    u64 d; asm("mul.rn.f32x2 %0, %1, %2;" : "=l"(d) : "l"(a), "l"(b)); return d;
}
__device__ __forceinline__ u64 add2(u64 a, u64 b) {
    u64 d; asm("add.rn.f32x2 %0, %1, %2;" : "=l"(d) : "l"(a), "l"(b)); return d;
}
__device__ __forceinline__ u64 pack2(float lo, float hi) {
    u64 d; asm("mov.b64 %0, {%1, %2};" : "=l"(d) : "f"(lo), "f"(hi)); return d;
}
__device__ __forceinline__ void unpack2(u64 v, float& lo, float& hi) {
    asm("mov.b64 {%0, %1}, %2;" : "=f"(lo), "=f"(hi) : "l"(v));
}

__global__ __launch_bounds__(NTHREADS, 4)
void attn_kernel(const float* __restrict__ x,
                 const float* __restrict__ Wq,
                 const float* __restrict__ Wk,
                 const float* __restrict__ Wv,
                 float* __restrict__ out)
{
    // x only, SoA over 4-key groups: group g = {x0[4], x1[4], x2[4]} float4s.
    // 512 * 48B = 24KB -> 4 CTAs/SM fit. Reused as split-K staging.
    __shared__ float4 sX[NGROUP * 3];

    const int bh  = blockIdx.x;        // b*8 + h
    const int b   = bh >> 3;
    const int h   = bh & 7;
    const int tid = threadIdx.x;

    const float* xb = x + b * SEQ * 3;

    // Prologue: transpose-copy x into 4-key SoA packs.
    for (int g = tid; g < NGROUP; g += NTHREADS) {
        const float4* xp = reinterpret_cast<const float4*>(xb + 12 * g);
        const float4 a = xp[0], c = xp[1], d = xp[2];
        sX[3 * g + 0] = make_float4(a.x, a.w, c.z, d.y);  // x0 of keys 4g..4g+3
        sX[3 * g + 1] = make_float4(a.y, c.x, c.w, d.z);  // x1
        sX[3 * g + 2] = make_float4(a.z, c.y, d.x, d.w);  // x2
    }
    __syncthreads();

    // Decomposition: duo owns queries (qA, qB); split selects key quarter.
    const int duo   = tid & 63;
    const int split = tid >> 6;        // 0..3 (warp-uniform -> LDS broadcast)
    const int qA = blockIdx.y * QCHUNK + 2 * duo;
    const int qB = qA + 1;

    // g = cs * (x_q Wq) Wk^T  so that  t_s = g . x_s  (== scale*log2e * Q.K).
    // No row-max pass (bounded scores; softmax shift-invariant; rel_err ~5e-7
    // across R3/R5/R6/R7).
    const float cs = 1.4426950408889634f * 0.5773502691896258f;
    const float* wqp = Wq + h * 9;
    const float* wkp = Wk + h * 9;
    float wq[9], wk[9];
#pragma unroll
    for (int i = 0; i < 9; i++) { wq[i] = __ldg(wqp + i); wk[i] = __ldg(wkp + i); }

    const float xa0 = xb[3 * qA + 0], xa1 = xb[3 * qA + 1], xa2 = xb[3 * qA + 2];
    const float xb0 = xb[3 * qB + 0], xb1 = xb[3 * qB + 1], xb2 = xb[3 * qB + 2];

    // Q[e] = sum_d xq[d] * Wq[d][e]   (Wq row-major [d][e] = wq[3d+e])
    const float QA0 = fmaf(xa2, wq[6], fmaf(xa1, wq[3], xa0 * wq[0]));
    const float QA1 = fmaf(xa2, wq[7], fmaf(xa1, wq[4], xa0 * wq[1]));
    const float QA2 = fmaf(xa2, wq[8], fmaf(xa1, wq[5], xa0 * wq[2]));
    const float QB0 = fmaf(xb2, wq[6], fmaf(xb1, wq[3], xb0 * wq[0]));
    const float QB1 = fmaf(xb2, wq[7], fmaf(xb1, wq[4], xb0 * wq[1]));
    const float QB2 = fmaf(xb2, wq[8], fmaf(xb1, wq[5], xb0 * wq[2]));
    // g[d] = cs * sum_e Q[e] * Wk[d][e]
    const float gA0 = cs * fmaf(QA2, wk[2], fmaf(QA1, wk[1], QA0 * wk[0]));
    const float gA1 = cs * fmaf(QA2, wk[5], fmaf(QA1, wk[4], QA0 * wk[3]));
    const float gA2 = cs * fmaf(QA2, wk[8], fmaf(QA1, wk[7], QA0 * wk[6]));
    const float gB0 = cs * fmaf(QB2, wk[2], fmaf(QB1, wk[1], QB0 * wk[0]));
    const float gB1 = cs * fmaf(QB2, wk[5], fmaf(QB1, wk[4], QB0 * wk[3]));
    const float gB2 = cs * fmaf(QB2, wk[8], fmaf(QB1, wk[7], QB0 * wk[6]));

    const u64 gA0p = pack2(gA0, gA0), gA1p = pack2(gA1, gA1), gA2p = pack2(gA2, gA2);
    const u64 gB0p = pack2(gB0, gB0), gB1p = pack2(gB1, gB1), gB2p = pack2(gB2, gB2);

    // Accumulators per query: den + S = sum e*x (3 dims); lo/hi key-pairs share
    // the same f32x2 accumulator (fewer regs).
    u64 dA = 0, sA0 = 0, sA1 = 0, sA2 = 0;
    u64 dB = 0, sB0 = 0, sB1 = 0, sB2 = 0;

    const ulonglong2* p = reinterpret_cast<const ulonglong2*>(sX) + 3 * (split * GPT);

#pragma unroll 4
    for (int it = 0; it < GPT; ++it) {
        const ulonglong2 x0 = p[0];   // dim0: pairs (k0,k1),(k2,k3)
        const ulonglong2 x1 = p[1];
        const ulonglong2 x2 = p[2];
        p += 3;

        // Query A
        {
            const u64 tl = fma2(gA0p, x0.x, fma2(gA1p, x1.x, mul2(gA2p, x2.x)));
            const u64 th = fma2(gA0p, x0.y, fma2(gA1p, x1.y, mul2(gA2p, x2.y)));
            float t0, t1, t2, t3;
            unpack2(tl, t0, t1); unpack2(th, t2, t3);
            const u64 el = pack2(ex2f(t0), ex2f(t1));
            const u64 eh = pack2(ex2f(t2), ex2f(t3));
            dA  = add2(dA, el);          dA  = add2(dA, eh);
            sA0 = fma2(el, x0.x, sA0);   sA0 = fma2(eh, x0.y, sA0);
            sA1 = fma2(el, x1.x, sA1);   sA1 = fma2(eh, x1.y, sA1);
            sA2 = fma2(el, x2.x, sA2);   sA2 = fma2(eh, x2.y, sA2);
        }
        // Query B
        {
            const u64 tl = fma2(gB0p, x0.x, fma2(gB1p, x1.x, mul2(gB2p, x2.x)));
            const u64 th = fma2(gB0p, x0.y, fma2(gB1p, x1.y, mul2(gB2p, x2.y)));
            float t0, t1, t2, t3;
            unpack2(tl, t0, t1); unpack2(th, t2, t3);
            const u64 el = pack2(ex2f(t0), ex2f(t1));
            const u64 eh = pack2(ex2f(t2), ex2f(t3));
            dB  = add2(dB, el);          dB  = add2(dB, eh);
            sB0 = fma2(el, x0.x, sB0);   sB0 = fma2(eh, x0.y, sB0);
            sB1 = fma2(el, x1.x, sB1);   sB1 = fma2(eh, x1.y, sB1);
            sB2 = fma2(el, x2.x, sB2);   sB2 = fma2(eh, x2.y, sB2);
        }
    }

    // Horizontal reduce u64 pairs to scalars.
    float lo, hi;
    unpack2(dA, lo, hi);  const float denA = lo + hi;
    unpack2(sA0, lo, hi); const float SA0 = lo + hi;
    unpack2(sA1, lo, hi); const float SA1 = lo + hi;
    unpack2(sA2, lo, hi); const float SA2 = lo + hi;
    unpack2(dB, lo, hi);  const float denB = lo + hi;
    unpack2(sB0, lo, hi); const float SB0 = lo + hi;
    unpack2(sB1, lo, hi); const float SB1 = lo + hi;
    unpack2(sB2, lo, hi); const float SB2 = lo + hi;

    // Split-K merge via reused smem: splits 1..3 stage; split 0 combines.
    __syncthreads();   // all x reads done
    float4* stage = reinterpret_cast<float4*>(sX);  // [3][64][2] float4 = 6KB
    if (split != 0) {
        float4* sp = stage + ((split - 1) * 64 + duo) * 2;
        sp[0] = make_float4(denA, SA0, SA1, SA2);
        sp[1] = make_float4(denB, SB0, SB1, SB2);
    }
    __syncthreads();
    if (split == 0) {
        float4 aA = make_float4(denA, SA0, SA1, SA2);
        float4 aB = make_float4(denB, SB0, SB1, SB2);
#pragma unroll
        for (int s = 0; s < 3; s++) {
            const float4* sp = stage + (s * 64 + duo) * 2;
            const float4 vA = sp[0];
            const float4 vB = sp[1];
            aA.x += vA.x; aA.y += vA.y; aA.z += vA.z; aA.w += vA.w;
            aB.x += vB.x; aB.y += vB.y; aB.z += vB.z; aB.w += vB.w;
        }
        // ctx[e] = (sum_d S[d] * Wv[d][e]) / den   (linearity of V-projection)
        const float* wvp = Wv + h * 9;
        float wv[9];
#pragma unroll
        for (int i = 0; i < 9; i++) wv[i] = __ldg(wvp + i);

        const float invA = rcpf(aA.x);
        const float invB = rcpf(aB.x);
        const float oA0 = fmaf(aA.w, wv[6], fmaf(aA.z, wv[3], aA.y * wv[0])) * invA;
        const float oA1 = fmaf(aA.w, wv[7], fmaf(aA.z, wv[4], aA.y * wv[1])) * invA;
        const float oA2 = fmaf(aA.w, wv[8], fmaf(aA.z, wv[5], aA.y * wv[2])) * invA;
        const float oB0 = fmaf(aB.w, wv[6], fmaf(aB.z, wv[3], aB.y * wv[0])) * invB;
        const float oB1 = fmaf(aB.w, wv[7], fmaf(aB.z, wv[4], aB.y * wv[1])) * invB;
        const float oB2 = fmaf(aB.w, wv[8], fmaf(aB.z, wv[5], aB.y * wv[2])) * invB;

        const int base = (bh * SEQ + qA) * 3;   // 6 consecutive floats, 8B-aligned
        const int dup  = BATCH * HEADS * SEQ * 3;
        float2* o1 = reinterpret_cast<float2*>(out + base);
        float2* o2 = reinterpret_cast<float2*>(out + dup + base);
        o1[0] = make_float2(oA0, oA1);
        o1[1] = make_float2(oA2, oB0);
        o1[2] = make_float2(oB1, oB2);
        o2[0] = make_float2(oA0, oA1);
        o2[1] = make_float2(oA2, oB0);
        o2[2] = make_float2(oB1, oB2);
    }
}

extern "C" void kernel_launch(void* const* d_in, const int* in_sizes, int n_in,
                              void* d_out, int out_size)
{
    const float* x  = (const float*)d_in[0];
    const float* Wq = (const float*)d_in[1];
    const float* Wk = (const float*)d_in[2];
    const float* Wv = (const float*)d_in[3];
    float* out = (float*)d_out;

    dim3 grid(BATCH * HEADS, NCHUNK);   // 32 x 16 = 512 CTAs, target 4/SM
    attn_kernel<<<grid, NTHREADS>>>(x, Wq, Wk, Wv, out);
}

// round 10
// speedup vs baseline: 1.2015x; 1.0972x over previous
#include <cuda_runtime.h>
#include <cuda_bf16.h>
#include <math_constants.h>

// Problem constants (fixed by the reference): B=4, H=8, S=2048, D=3
#define BATCH 4
#define HEADS 8
#define SEQ   2048
#define NGROUP (SEQ / 4)   // 512 groups of 4 keys
#define NCHUNK 32          // q-chunks per (b,h)
#define QCHUNK 64          // queries per CTA
#define NTHREADS 128       // thread = (duo 0..31 [2 queries], split 0..3)
#define GPT (NGROUP / 4)   // 128 groups per split

typedef unsigned long long u64;

__device__ __forceinline__ float ex2f(float x) {
    float y; asm("ex2.approx.f32 %0, %1;" : "=f"(y) : "f"(x)); return y;
}
__device__ __forceinline__ float rcpf(float x) {
    float y; asm("rcp.approx.f32 %0, %1;" : "=f"(y) : "f"(x)); return y;
}
__device__ __forceinline__ u64 fma2(u64 a, u64 b, u64 c) {
    u64 d; asm("fma.rn.f32x2 %0, %1, %2, %3;" : "=l"(d) : "l"(a), "l"(b), "l"(c)); return d;
}
__device__ __forceinline__ u64 mul2(u64 a, u64 b) {
    u64 d; asm("mul.rn.f32x2 %0, %1, %2;" : "=l"(d) : "l"(a), "l"(b)); return d;
}
__device__ __forceinline__ u64 add2(u64 a, u64 b) {
    u64 d; asm("add.rn.f32x2 %0, %1, %2;" : "=l"(d) : "l"(a), "l"(b)); return d;
}
__device__ __forceinline__ u64 pack2(float lo, float hi) {
    u64 d; asm("mov.b64 %0, {%1, %2};" : "=l"(d) : "f"(lo), "f"(hi)); return d;
}
__device__ __forceinline__ void unpack2(u64 v, float& lo, float& hi) {
    asm("mov.b64 {%0, %1}, %2;" : "=f"(lo), "=f"(hi) : "l"(v));
}

__global__ __launch_bounds__(NTHREADS, 8)
void attn_kernel(const float* __restrict__ x,
                 const float* __restrict__ Wq,
                 const float* __restrict__ Wk,
                 const float* __restrict__ Wv,
                 float* __restrict__ out)
{
    // x only, SoA over 4-key groups: group g = {x0[4], x1[4], x2[4]} float4s.
    // 512 * 48B = 24KB -> 8 CTAs/SM (192KB of 228KB). Reused as staging.
    __shared__ float4 sX[NGROUP * 3];

    const int bh  = blockIdx.x;        // b*8 + h
    const int b   = bh >> 3;
    const int h   = bh & 7;
    const int tid = threadIdx.x;

    const float* xb = x + b * SEQ * 3;

    // Prologue: transpose-copy x into 4-key SoA packs (4 groups per thread).
    for (int g = tid; g < NGROUP; g += NTHREADS) {
        const float4* xp = reinterpret_cast<const float4*>(xb + 12 * g);
        const float4 a = xp[0], c = xp[1], d = xp[2];
        sX[3 * g + 0] = make_float4(a.x, a.w, c.z, d.y);  // x0 of keys 4g..4g+3
        sX[3 * g + 1] = make_float4(a.y, c.x, c.w, d.z);  // x1
        sX[3 * g + 2] = make_float4(a.z, c.y, d.x, d.w);  // x2
    }
    __syncthreads();

    // Decomposition: duo owns queries (qA, qB); split selects key quarter.
    const int duo   = tid & 31;
    const int split = tid >> 5;        // 0..3 (warp index -> warp-uniform)
    const int qA = blockIdx.y * QCHUNK + 2 * duo;
    const int qB = qA + 1;

    // g = cs * (x_q Wq) Wk^T  so that  t_s = g . x_s  (== scale*log2e * Q.K).
    // No row-max pass (bounded scores; softmax shift-invariant; rel_err ~4e-7).
    const float cs = 1.4426950408889634f * 0.5773502691896258f;
    const float* wqp = Wq + h * 9;
    const float* wkp = Wk + h * 9;
    float wq[9], wk[9];
#pragma unroll
    for (int i = 0; i < 9; i++) { wq[i] = __ldg(wqp + i); wk[i] = __ldg(wkp + i); }

    const float xa0 = xb[3 * qA + 0], xa1 = xb[3 * qA + 1], xa2 = xb[3 * qA + 2];
    const float xb0 = xb[3 * qB + 0], xb1 = xb[3 * qB + 1], xb2 = xb[3 * qB + 2];

    // Q[e] = sum_d xq[d] * Wq[d][e]   (Wq row-major [d][e] = wq[3d+e])
    const float QA0 = fmaf(xa2, wq[6], fmaf(xa1, wq[3], xa0 * wq[0]));
    const float QA1 = fmaf(xa2, wq[7], fmaf(xa1, wq[4], xa0 * wq[1]));
    const float QA2 = fmaf(xa2, wq[8], fmaf(xa1, wq[5], xa0 * wq[2]));
    const float QB0 = fmaf(xb2, wq[6], fmaf(xb1, wq[3], xb0 * wq[0]));
    const float QB1 = fmaf(xb2, wq[7], fmaf(xb1, wq[4], xb0 * wq[1]));
    const float QB2 = fmaf(xb2, wq[8], fmaf(xb1, wq[5], xb0 * wq[2]));
    // g[d] = cs * sum_e Q[e] * Wk[d][e]
    const float gA0 = cs * fmaf(QA2, wk[2], fmaf(QA1, wk[1], QA0 * wk[0]));
    const float gA1 = cs * fmaf(QA2, wk[5], fmaf(QA1, wk[4], QA0 * wk[3]));
    const float gA2 = cs * fmaf(QA2, wk[8], fmaf(QA1, wk[7], QA0 * wk[6]));
    const float gB0 = cs * fmaf(QB2, wk[2], fmaf(QB1, wk[1], QB0 * wk[0]));
    const float gB1 = cs * fmaf(QB2, wk[5], fmaf(QB1, wk[4], QB0 * wk[3]));
    const float gB2 = cs * fmaf(QB2, wk[8], fmaf(QB1, wk[7], QB0 * wk[6]));

    const u64 gA0p = pack2(gA0, gA0), gA1p = pack2(gA1, gA1), gA2p = pack2(gA2, gA2);
    const u64 gB0p = pack2(gB0, gB0), gB1p = pack2(gB1, gB1), gB2p = pack2(gB2, gB2);

    // Accumulators per query: den + S = sum e*x (3 dims); lo/hi key-pairs share
    // the same f32x2 accumulator.
    u64 dA = 0, sA0 = 0, sA1 = 0, sA2 = 0;
    u64 dB = 0, sB0 = 0, sB1 = 0, sB2 = 0;

    const ulonglong2* p = reinterpret_cast<const ulonglong2*>(sX) + 3 * (split * GPT);

#pragma unroll 4
    for (int it = 0; it < GPT; ++it) {
        const ulonglong2 x0 = p[0];   // dim0: pairs (k0,k1),(k2,k3)
        const ulonglong2 x1 = p[1];
        const ulonglong2 x2 = p[2];
        p += 3;

        // Query A
        {
            const u64 tl = fma2(gA0p, x0.x, fma2(gA1p, x1.x, mul2(gA2p, x2.x)));
            const u64 th = fma2(gA0p, x0.y, fma2(gA1p, x1.y, mul2(gA2p, x2.y)));
            float t0, t1, t2, t3;
            unpack2(tl, t0, t1); unpack2(th, t2, t3);
            const u64 el = pack2(ex2f(t0), ex2f(t1));
            const u64 eh = pack2(ex2f(t2), ex2f(t3));
            dA  = add2(dA, el);          dA  = add2(dA, eh);
            sA0 = fma2(el, x0.x, sA0);   sA0 = fma2(eh, x0.y, sA0);
            sA1 = fma2(el, x1.x, sA1);   sA1 = fma2(eh, x1.y, sA1);
            sA2 = fma2(el, x2.x, sA2);   sA2 = fma2(eh, x2.y, sA2);
        }
        // Query B
        {
            const u64 tl = fma2(gB0p, x0.x, fma2(gB1p, x1.x, mul2(gB2p, x2.x)));
            const u64 th = fma2(gB0p, x0.y, fma2(gB1p, x1.y, mul2(gB2p, x2.y)));
            float t0, t1, t2, t3;
            unpack2(tl, t0, t1); unpack2(th, t2, t3);
            const u64 el = pack2(ex2f(t0), ex2f(t1));
            const u64 eh = pack2(ex2f(t2), ex2f(t3));
            dB  = add2(dB, el);          dB  = add2(dB, eh);
            sB0 = fma2(el, x0.x, sB0);   sB0 = fma2(eh, x0.y, sB0);
            sB1 = fma2(el, x1.x, sB1);   sB1 = fma2(eh, x1.y, sB1);
            sB2 = fma2(el, x2.x, sB2);   sB2 = fma2(eh, x2.y, sB2);
        }
    }

    // Horizontal reduce u64 pairs to scalars.
    float lo, hi;
    unpack2(dA, lo, hi);  const float denA = lo + hi;
    unpack2(sA0, lo, hi); const float SA0 = lo + hi;
    unpack2(sA1, lo, hi); const float SA1 = lo + hi;
    unpack2(sA2, lo, hi); const float SA2 = lo + hi;
    unpack2(dB, lo, hi);  const float denB = lo + hi;
    unpack2(sB0, lo, hi); const float SB0 = lo + hi;
    unpack2(sB1, lo, hi); const float SB1 = lo + hi;
    unpack2(sB2, lo, hi); const float SB2 = lo + hi;

    // Split-K merge via reused smem: splits 1..3 stage; split 0 combines.
    __syncthreads();   // all x reads done
    float4* stage = reinterpret_cast<float4*>(sX);  // [3][32][2] float4 = 3KB
    if (split != 0) {
        float4* sp = stage + ((split - 1) * 32 + duo) * 2;
        sp[0] = make_float4(denA, SA0, SA1, SA2);
        sp[1] = make_float4(denB, SB0, SB1, SB2);
    }
    __syncthreads();
    if (split == 0) {
        float4 aA = make_float4(denA, SA0, SA1, SA2);
        float4 aB = make_float4(denB, SB0, SB1, SB2);
#pragma unroll
        for (int s = 0; s < 3; s++) {
            const float4* sp = stage + (s * 32 + duo) * 2;
            const float4 vA = sp[0];
            const float4 vB = sp[1];
            aA.x += vA.x; aA.y += vA.y; aA.z += vA.z; aA.w += vA.w;
            aB.x += vB.x; aB.y += vB.y; aB.z += vB.z; aB.w += vB.w;
        }
        // ctx[e] = (sum_d S[d] * Wv[d][e]) / den   (linearity of V-projection)
        const float* wvp = Wv + h * 9;
        float wv[9];
#pragma unroll
        for (int i = 0; i < 9; i++) wv[i] = __ldg(wvp + i);

        const float invA = rcpf(aA.x);
        const float invB = rcpf(aB.x);
        const float oA0 = fmaf(aA.w, wv[6], fmaf(aA.z, wv[3], aA.y * wv[0])) * invA;
        const float oA1 = fmaf(aA.w, wv[7], fmaf(aA.z, wv[4], aA.y * wv[1])) * invA;
        const float oA2 = fmaf(aA.w, wv[8], fmaf(aA.z, wv[5], aA.y * wv[2])) * invA;
        const float oB0 = fmaf(aB.w, wv[6], fmaf(aB.z, wv[3], aB.y * wv[0])) * invB;
        const float oB1 = fmaf(aB.w, wv[7], fmaf(aB.z, wv[4], aB.y * wv[1])) * invB;
        const float oB2 = fmaf(aB.w, wv[8], fmaf(aB.z, wv[5], aB.y * wv[2])) * invB;

        const int base = (bh * SEQ + qA) * 3;   // 6 consecutive floats, 8B-aligned
        const int dup  = BATCH * HEADS * SEQ * 3;
        float2* o1 = reinterpret_cast<float2*>(out + base);
        float2* o2 = reinterpret_cast<float2*>(out + dup + base);
        o1[0] = make_float2(oA0, oA1);
        o1[1] = make_float2(oA2, oB0);
        o1[2] = make_float2(oB1, oB2);
        o2[0] = make_float2(oA0, oA1);
        o2[1] = make_float2(oA2, oB0);
        o2[2] = make_float2(oB1, oB2);
    }
}

extern "C" void kernel_launch(void* const* d_in, const int* in_sizes, int n_in,
                              void* d_out, int out_size)
{
    const float* x  = (const float*)d_in[0];
    const float* Wq = (const float*)d_in[1];
    const float* Wk = (const float*)d_in[2];
    const float* Wv = (const float*)d_in[3];
    float* out = (float*)d_out;

    dim3 grid(BATCH * HEADS, NCHUNK);   // 32 x 32 = 1024 CTAs, target 8/SM
    attn_kernel<<<grid, NTHREADS>>>(x, Wq, Wk, Wv, out);
}